// round 7
// baseline (speedup 1.0000x reference)
#include <cuda_runtime.h>
#include <cuda_bf16.h>
#include <cstdint>

#define BATCH 1024
#define MF 1024
#define NF 512
#define LAMBDv 0.2f
#define TOL2 1e-8f
#define MAX_ITERS 100

// iteration GEMM tiling: CTA tile 64(M) x 64(N), K chunks of 64
#define KC 64
#define NCHUNK (MF / KC)            // 16
#define SROW 72                     // smem row stride in bf16 (144B, ldmatrix conflict-free)
#define TILEB (64 * SROW * 2)       // 9216 per tile (A or B, hi or lo)
#define STAGEB (4 * TILEB)          // 36864
#define DYN_SMEM (2 * STAGEB)       // 73728

// ---------------- device scratch ----------------
__device__ __align__(256) float g_Adb[BATCH * MF];
__device__ __align__(256) float g_u[BATCH * MF];
__device__ __align__(256) float g_v[BATCH * MF];
__device__ __align__(256) __nv_bfloat16 g_behi[2][BATCH * MF];
__device__ __align__(256) __nv_bfloat16 g_belo[2][BATCH * MF];
__device__ __align__(256) __nv_bfloat16 g_mThi[MF * MF];
__device__ __align__(256) __nv_bfloat16 g_mTlo[MF * MF];
__device__ float g_dx2p[BATCH * 16];
__device__ float g_x2p[BATCH * 16];
__device__ int g_solved[BATCH];
__device__ int g_stripe_done[16];

// ---------------- helpers ----------------
__device__ __forceinline__ uint32_t smem_u32(const void* p) {
    uint32_t a;
    asm("{ .reg .u64 t; cvta.to.shared.u64 t, %1; cvt.u32.u64 %0, t; }" : "=r"(a) : "l"(p));
    return a;
}
__device__ __forceinline__ void ldm_x4(unsigned* r, uint32_t addr) {
    asm volatile("ldmatrix.sync.aligned.m8n8.x4.shared.b16 {%0,%1,%2,%3}, [%4];"
        : "=r"(r[0]), "=r"(r[1]), "=r"(r[2]), "=r"(r[3]) : "r"(addr));
}
__device__ __forceinline__ void cpa16(uint32_t dst, const void* src) {
    asm volatile("cp.async.cg.shared.global [%0], [%1], 16;" :: "r"(dst), "l"(src));
}
#define CP_COMMIT() asm volatile("cp.async.commit_group;" ::: "memory")
#define CP_WAIT(n)  asm volatile("cp.async.wait_group %0;" :: "n"(n) : "memory")

__device__ __forceinline__ void mma16816(float* c, const unsigned* a, const unsigned* b) {
    asm volatile(
        "mma.sync.aligned.m16n8k16.row.col.f32.bf16.bf16.f32 "
        "{%0,%1,%2,%3}, {%4,%5,%6,%7}, {%8,%9}, {%0,%1,%2,%3};"
        : "+f"(c[0]), "+f"(c[1]), "+f"(c[2]), "+f"(c[3])
        : "r"(a[0]), "r"(a[1]), "r"(a[2]), "r"(a[3]), "r"(b[0]), "r"(b[1]));
}
__device__ __forceinline__ void bsplit(float x, __nv_bfloat16& h, __nv_bfloat16& l) {
    h = __float2bfloat16(x);
    l = __float2bfloat16(x - __bfloat162float(h));
}

// ---------------- init ----------------
__global__ void init_kernel() {
    int i = blockIdx.x * blockDim.x + threadIdx.x;  // BATCH*MF/4
    float4 z = make_float4(0.f, 0.f, 0.f, 0.f);
    ((float4*)g_u)[i] = z;
    ((float4*)g_v)[i] = z;
    if (i < BATCH) g_solved[i] = 0;
    if (i < 16) g_stripe_done[i] = 0;
}

// ---------------- Minv -> transposed bf16 hi/lo split ----------------
__global__ void prep_minv(const float* __restrict__ Minv) {
    __shared__ float t[32][33];
    int bx = blockIdx.x * 32, by = blockIdx.y * 32;
    for (int i = threadIdx.y; i < 32; i += 8)
        t[i][threadIdx.x] = Minv[(size_t)(by + i) * MF + bx + threadIdx.x];
    __syncthreads();
    for (int i = threadIdx.y; i < 32; i += 8) {
        int n = bx + i, k = by + threadIdx.x;
        __nv_bfloat16 h, l;
        bsplit(t[threadIdx.x][i], h, l);  // Minv[k][n] -> MinvT[n][k]
        g_mThi[(size_t)n * MF + k] = h;
        g_mTlo[(size_t)n * MF + k] = l;
    }
}

// ---------------- A_dot_b = x @ W^T ; seeds beff[0] split (u=v=0) ----------------
__global__ void gemm_nt_kernel(const float* __restrict__ X, const float* __restrict__ W) {
    __shared__ float As[16][64];
    __shared__ float Bs[16][64];
    int tid = threadIdx.x;
    int row0 = blockIdx.y * 64, col0 = blockIdx.x * 64;
    int lr = tid >> 2, kq = tid & 3;
    int tm = tid >> 4, tn = tid & 15;
    float acc[4][4] = {};
    for (int k0 = 0; k0 < NF; k0 += 16) {
        float4 a4 = *(const float4*)(X + (size_t)(row0 + lr) * NF + k0 + kq * 4);
        float4 b4 = *(const float4*)(W + (size_t)(col0 + lr) * NF + k0 + kq * 4);
        __syncthreads();
        As[kq * 4 + 0][lr] = a4.x; As[kq * 4 + 1][lr] = a4.y;
        As[kq * 4 + 2][lr] = a4.z; As[kq * 4 + 3][lr] = a4.w;
        Bs[kq * 4 + 0][lr] = b4.x; Bs[kq * 4 + 1][lr] = b4.y;
        Bs[kq * 4 + 2][lr] = b4.z; Bs[kq * 4 + 3][lr] = b4.w;
        __syncthreads();
#pragma unroll
        for (int kk = 0; kk < 16; kk++) {
            float4 av = *(const float4*)&As[kk][tm * 4];
            float4 bv = *(const float4*)&Bs[kk][tn * 4];
            float a[4] = {av.x, av.y, av.z, av.w};
            float b[4] = {bv.x, bv.y, bv.z, bv.w};
#pragma unroll
            for (int i = 0; i < 4; i++)
#pragma unroll
                for (int j = 0; j < 4; j++) acc[i][j] += a[i] * b[j];
        }
    }
#pragma unroll
    for (int i = 0; i < 4; i++) {
        size_t base = (size_t)(row0 + tm * 4 + i) * MF + col0 + tn * 4;
        *(float4*)(g_Adb + base) = make_float4(acc[i][0], acc[i][1], acc[i][2], acc[i][3]);
#pragma unroll
        for (int j = 0; j < 4; j++) {
            __nv_bfloat16 h, l;
            bsplit(acc[i][j], h, l);
            g_behi[0][base + j] = h;
            g_belo[0][base + j] = l;
        }
    }
}

// ---------------- per-iteration mma.sync GEMM + fused ADMM epilogue ----------------
// Tile 64(M) x 64(N); 4 warps as 2(M) x 2(N), warp tile 32x32.
// xk[r,n] = sum_k beff[r,k] * MinvT[n,k]; bf16 hi/lo 3-pass into fp32 frags.
__global__ void __launch_bounds__(128, 2) admm_iter(int p) {
    if (g_stripe_done[blockIdx.y]) return;
    extern __shared__ __align__(16) char sraw[];
    __shared__ float red_dx[64][2];
    __shared__ float red_x2[64][2];

    const int tid = threadIdx.x;
    const int lane = tid & 31;
    const int w = tid >> 5;
    const int warp_m = w & 1;   // 2 warps x 32 rows
    const int warp_n = w >> 1;  // 2 warps x 32 cols
    const int row0 = blockIdx.y * 64;
    const int col0 = blockIdx.x * 64;
    const int pn = p ^ 1;

    const uint32_t sb = smem_u32(sraw);

    // cp.async coords: 4 x 16B segments per tile per thread (128 thr x 4 x 16B = 8KB)
    const int cs = tid & 7;

    // issue chunk 0
    {
        const __nv_bfloat16* ah = g_behi[p];
        const __nv_bfloat16* al = g_belo[p];
#pragma unroll
        for (int j = 0; j < 4; j++) {
            int row = (tid + j * 128) >> 3;
            uint32_t doff = (uint32_t)row * (SROW * 2) + cs * 16;
            const size_t aoff = (size_t)(row0 + row) * MF + cs * 8;
            const size_t boff = (size_t)(col0 + row) * MF + cs * 8;
            cpa16(sb + doff, ah + aoff);
            cpa16(sb + TILEB + doff, al + aoff);
            cpa16(sb + 2 * TILEB + doff, g_mThi + boff);
            cpa16(sb + 3 * TILEB + doff, g_mTlo + boff);
        }
    }
    CP_COMMIT();

    float c[2][4][4] = {};
    // ldmatrix per-thread offsets
    const uint32_t a_off = (uint32_t)(warp_m * 32 + (lane & 15)) * (SROW * 2) + (lane >> 4) * 16;
    const uint32_t b_off = (uint32_t)(warp_n * 32 + (lane & 7) + ((lane >> 4) & 1) * 8) * (SROW * 2)
                         + ((lane >> 3) & 1) * 16;

    for (int t = 0; t < NCHUNK; t++) {
        int s = t & 1;
        if (t + 1 < NCHUNK) {
            int kb = (t + 1) * KC;
            uint32_t stb = sb + ((t + 1) & 1) * STAGEB;
            const __nv_bfloat16* ah = g_behi[p];
            const __nv_bfloat16* al = g_belo[p];
#pragma unroll
            for (int j = 0; j < 4; j++) {
                int row = (tid + j * 128) >> 3;
                uint32_t doff = (uint32_t)row * (SROW * 2) + cs * 16;
                const size_t aoff = (size_t)(row0 + row) * MF + kb + cs * 8;
                const size_t boff = (size_t)(col0 + row) * MF + kb + cs * 8;
                cpa16(stb + doff, ah + aoff);
                cpa16(stb + TILEB + doff, al + aoff);
                cpa16(stb + 2 * TILEB + doff, g_mThi + boff);
                cpa16(stb + 3 * TILEB + doff, g_mTlo + boff);
            }
            CP_COMMIT();
            CP_WAIT(1);
        } else {
            CP_WAIT(0);
        }
        __syncthreads();

        const uint32_t Ah = sb + s * STAGEB;
        const uint32_t Al = Ah + TILEB;
        const uint32_t Bh = Ah + 2 * TILEB;
        const uint32_t Bl = Ah + 3 * TILEB;
#pragma unroll
        for (int kk = 0; kk < 4; kk++) {
            const uint32_t kb32 = kk * 32;  // 16 bf16 = 32B
            unsigned ah[2][4], al[2][4], bh[2][4], bl[2][4];
#pragma unroll
            for (int fm = 0; fm < 2; fm++) {
                uint32_t ao = a_off + (uint32_t)(fm * 16) * (SROW * 2) + kb32;
                ldm_x4(ah[fm], Ah + ao);
                ldm_x4(al[fm], Al + ao);
            }
#pragma unroll
            for (int pr = 0; pr < 2; pr++) {
                uint32_t bo = b_off + (uint32_t)(pr * 16) * (SROW * 2) + kb32;
                ldm_x4(bh[pr], Bh + bo);
                ldm_x4(bl[pr], Bl + bo);
            }
#pragma unroll
            for (int fm = 0; fm < 2; fm++)
#pragma unroll
                for (int fn = 0; fn < 4; fn++) {
                    const unsigned* ph = &bh[fn >> 1][(fn & 1) * 2];
                    const unsigned* pl = &bl[fn >> 1][(fn & 1) * 2];
                    mma16816(c[fm][fn], ah[fm], ph);
                    mma16816(c[fm][fn], ah[fm], pl);
                    mma16816(c[fm][fn], al[fm], ph);
                }
        }
        __syncthreads();
    }

    // ---- fused ADMM epilogue on register fragments ----
    float pdx[2][2] = {}, px2[2][2] = {};
#pragma unroll
    for (int fm = 0; fm < 2; fm++) {
#pragma unroll
        for (int rs = 0; rs < 2; rs++) {
            int r = row0 + warp_m * 32 + fm * 16 + rs * 8 + (lane >> 2);
            int solved = g_solved[r];
            float ldx = 0.f, lx2 = 0.f;
#pragma unroll
            for (int fn = 0; fn < 4; fn++) {
                int cc = col0 + warp_n * 32 + fn * 8 + (lane & 3) * 2;
                size_t base = (size_t)r * MF + cc;
                float2 u2 = *(const float2*)(g_u + base);
                float2 v2 = *(const float2*)(g_v + base);
                float2 a2 = *(const float2*)(g_Adb + base);
                float uu[2] = {u2.x, u2.y}, vv[2] = {v2.x, v2.y}, aa[2] = {a2.x, a2.y};
                float un[2], vn[2];
#pragma unroll
                for (int jj = 0; jj < 2; jj++) {
                    float xk = c[fm][fn][rs * 2 + jj];
                    float tt = xk + uu[jj];
                    float av = fabsf(tt) - LAMBDv;
                    float sft = (av > 0.f) ? copysignf(av, tt) : 0.f;
                    if (!solved) {
                        un[jj] = tt - sft;
                        vn[jj] = sft;
                        float d = sft - vv[jj];
                        ldx += d * d;
                        lx2 += sft * sft;
                    } else {
                        un[jj] = uu[jj];
                        vn[jj] = vv[jj];
                    }
                }
                if (!solved) {
                    *(float2*)(g_u + base) = make_float2(un[0], un[1]);
                    *(float2*)(g_v + base) = make_float2(vn[0], vn[1]);
                }
                __nv_bfloat16 h0, l0, h1, l1;
                bsplit(aa[0] + vn[0] - un[0], h0, l0);
                bsplit(aa[1] + vn[1] - un[1], h1, l1);
                *(__nv_bfloat162*)(g_behi[pn] + base) = __halves2bfloat162(h0, h1);
                *(__nv_bfloat162*)(g_belo[pn] + base) = __halves2bfloat162(l0, l1);
            }
            pdx[fm][rs] = ldx;
            px2[fm][rs] = lx2;
        }
    }
    // reduce across the 4 column-lanes of each row
#pragma unroll
    for (int fm = 0; fm < 2; fm++) {
#pragma unroll
        for (int rs = 0; rs < 2; rs++) {
            float a = pdx[fm][rs], b = px2[fm][rs];
            a += __shfl_xor_sync(0xffffffffu, a, 1);
            a += __shfl_xor_sync(0xffffffffu, a, 2);
            b += __shfl_xor_sync(0xffffffffu, b, 1);
            b += __shfl_xor_sync(0xffffffffu, b, 2);
            if ((lane & 3) == 0) {
                int rl = warp_m * 32 + fm * 16 + rs * 8 + (lane >> 2);
                red_dx[rl][warp_n] = a;
                red_x2[rl][warp_n] = b;
            }
        }
    }
    __syncthreads();
    if (tid < 64) {
        int r = row0 + tid;
        g_dx2p[r * 16 + blockIdx.x] = red_dx[tid][0] + red_dx[tid][1];
        g_x2p[r * 16 + blockIdx.x] = red_x2[tid][0] + red_x2[tid][1];
    }
}

// ---------------- convergence flags + stripe-done ----------------
__global__ void converge_kernel() {
    int stripe = blockIdx.x;
    int r = stripe * 64 + threadIdx.x;
    __shared__ int cnt;
    if (threadIdx.x == 0) cnt = 0;
    __syncthreads();
    int slv = g_solved[r];
    if (!slv) {
        float sdx = 0.f, sx2 = 0.f;
#pragma unroll
        for (int j = 0; j < 16; j++) { sdx += g_dx2p[r * 16 + j]; sx2 += g_x2p[r * 16 + j]; }
        if (sdx < TOL2 * sx2) { g_solved[r] = 1; slv = 1; }
    }
    if (!slv) atomicAdd(&cnt, 1);
    __syncthreads();
    if (threadIdx.x == 0) g_stripe_done[stripe] = (cnt == 0);
}

// ---------------- enc = solved ? v : 0 ----------------
__global__ void finalize_enc(float* __restrict__ enc) {
    int i = blockIdx.x * blockDim.x + threadIdx.x;  // BATCH*MF/4
    int row = i / (MF / 4);
    float4 vv = ((const float4*)g_v)[i];
    float4 z = make_float4(0.f, 0.f, 0.f, 0.f);
    ((float4*)enc)[i] = g_solved[row] ? vv : z;
}

// ---------------- decoded = encoded @ W ----------------
__global__ void gemm_decode_kernel(const float* __restrict__ W, const float* __restrict__ enc,
                                   float* __restrict__ dec) {
    __shared__ float As[16][64];
    __shared__ float Bs[16][64];
    int tid = threadIdx.x;
    int row0 = blockIdx.y * 64, col0 = blockIdx.x * 64;
    int lr = tid >> 2, kq = tid & 3;
    int kr = tid >> 4, nq = tid & 15;
    int tm = tid >> 4, tn = tid & 15;
    float acc[4][4] = {};
    for (int k0 = 0; k0 < MF; k0 += 16) {
        float4 a4 = *(const float4*)(enc + (size_t)(row0 + lr) * MF + k0 + kq * 4);
        float4 b4 = *(const float4*)(W + (size_t)(k0 + kr) * NF + col0 + nq * 4);
        __syncthreads();
        As[kq * 4 + 0][lr] = a4.x; As[kq * 4 + 1][lr] = a4.y;
        As[kq * 4 + 2][lr] = a4.z; As[kq * 4 + 3][lr] = a4.w;
        *(float4*)&Bs[kr][nq * 4] = b4;
        __syncthreads();
#pragma unroll
        for (int kk = 0; kk < 16; kk++) {
            float4 av = *(const float4*)&As[kk][tm * 4];
            float4 bv = *(const float4*)&Bs[kk][tn * 4];
            float a[4] = {av.x, av.y, av.z, av.w};
            float b[4] = {bv.x, bv.y, bv.z, bv.w};
#pragma unroll
            for (int i = 0; i < 4; i++)
#pragma unroll
                for (int j = 0; j < 4; j++) acc[i][j] += a[i] * b[j];
        }
    }
#pragma unroll
    for (int i = 0; i < 4; i++) {
        float4 o = make_float4(acc[i][0], acc[i][1], acc[i][2], acc[i][3]);
        *(float4*)(dec + (size_t)(row0 + tm * 4 + i) * NF + col0 + tn * 4) = o;
    }
}

// ---------------- launch ----------------
extern "C" void kernel_launch(void* const* d_in, const int* in_sizes, int n_in,
                              void* d_out, int out_size) {
    const float* x = (const float*)d_in[0];      // (1024, 512)
    const float* w = (const float*)d_in[1];      // (1024, 512)
    const float* Minv = (const float*)d_in[2];   // (1024, 1024)
    float* out = (float*)d_out;
    float* enc = out;
    float* dec = out + BATCH * MF;

    static int attr_done = 0;
    if (!attr_done) {
        cudaFuncSetAttribute(admm_iter, cudaFuncAttributeMaxDynamicSharedMemorySize, DYN_SMEM);
        attr_done = 1;
    }

    init_kernel<<<BATCH * MF / 4 / 256, 256>>>();
    prep_minv<<<dim3(32, 32), dim3(32, 8)>>>(Minv);
    gemm_nt_kernel<<<dim3(MF / 64, BATCH / 64), 256>>>(x, w);

    for (int it = 0; it < MAX_ITERS; it++) {
        admm_iter<<<dim3(16, 16), 128, DYN_SMEM>>>(it & 1);
        converge_kernel<<<16, 64>>>();
    }

    finalize_enc<<<BATCH * MF / 4 / 256, 256>>>(enc);
    gemm_decode_kernel<<<dim3(NF / 64, BATCH / 64), 256>>>(w, enc, dec);
}

// round 8
// speedup vs baseline: 1.0057x; 1.0057x over previous
#include <cuda_runtime.h>
#include <cuda_bf16.h>
#include <cstdint>

#define BATCH 1024
#define MF 1024
#define NF 512
#define LAMBDv 0.2f
#define TOL2 1e-8f
#define MAX_ITERS 100

// iteration GEMM tiling: CTA tile 64(M) x 64(N), K chunks of 64
#define KC 64
#define NCHUNK (MF / KC)            // 16
#define SROW 72                     // smem row stride in bf16 (144B, ldmatrix conflict-free)
#define SROW2 (SROW * 2)
#define TILEB (64 * SROW2)          // 9216 per tile (A or B, hi or lo)
#define STAGEB (4 * TILEB)          // 36864
#define DYN_SMEM (2 * STAGEB)       // 73728

// ---------------- device scratch ----------------
__device__ __align__(256) float g_Adb[BATCH * MF];
__device__ __align__(256) float g_u[BATCH * MF];
__device__ __align__(256) float g_v[BATCH * MF];
__device__ __align__(256) __nv_bfloat16 g_behi[2][BATCH * MF];
__device__ __align__(256) __nv_bfloat16 g_belo[2][BATCH * MF];
__device__ __align__(256) __nv_bfloat16 g_mThi[MF * MF];
__device__ __align__(256) __nv_bfloat16 g_mTlo[MF * MF];
__device__ float g_dx2p[BATCH * 16];
__device__ float g_x2p[BATCH * 16];
__device__ int g_solved[BATCH];
__device__ int g_stripe_done[16];

// ---------------- helpers ----------------
__device__ __forceinline__ uint32_t smem_u32(const void* p) {
    uint32_t a;
    asm("{ .reg .u64 t; cvta.to.shared.u64 t, %1; cvt.u32.u64 %0, t; }" : "=r"(a) : "l"(p));
    return a;
}
__device__ __forceinline__ void ldm_x4(unsigned* r, uint32_t addr) {
    asm volatile("ldmatrix.sync.aligned.m8n8.x4.shared.b16 {%0,%1,%2,%3}, [%4];"
        : "=r"(r[0]), "=r"(r[1]), "=r"(r[2]), "=r"(r[3]) : "r"(addr));
}
__device__ __forceinline__ void cpa16(uint32_t dst, const void* src) {
    asm volatile("cp.async.cg.shared.global [%0], [%1], 16;" :: "r"(dst), "l"(src));
}
#define CP_COMMIT() asm volatile("cp.async.commit_group;" ::: "memory")
#define CP_WAIT(n)  asm volatile("cp.async.wait_group %0;" :: "n"(n) : "memory")

__device__ __forceinline__ void mma16816(float* c, const unsigned* a, const unsigned* b) {
    asm volatile(
        "mma.sync.aligned.m16n8k16.row.col.f32.bf16.bf16.f32 "
        "{%0,%1,%2,%3}, {%4,%5,%6,%7}, {%8,%9}, {%0,%1,%2,%3};"
        : "+f"(c[0]), "+f"(c[1]), "+f"(c[2]), "+f"(c[3])
        : "r"(a[0]), "r"(a[1]), "r"(a[2]), "r"(a[3]), "r"(b[0]), "r"(b[1]));
}
__device__ __forceinline__ void bsplit(float x, __nv_bfloat16& h, __nv_bfloat16& l) {
    h = __float2bfloat16(x);
    l = __float2bfloat16(x - __bfloat162float(h));
}

// ---------------- init ----------------
__global__ void init_kernel() {
    int i = blockIdx.x * blockDim.x + threadIdx.x;  // BATCH*MF/4
    float4 z = make_float4(0.f, 0.f, 0.f, 0.f);
    ((float4*)g_u)[i] = z;
    ((float4*)g_v)[i] = z;
    if (i < BATCH) g_solved[i] = 0;
    if (i < 16) g_stripe_done[i] = 0;
}

// ---------------- Minv -> transposed bf16 hi/lo split ----------------
__global__ void prep_minv(const float* __restrict__ Minv) {
    __shared__ float t[32][33];
    int bx = blockIdx.x * 32, by = blockIdx.y * 32;
    for (int i = threadIdx.y; i < 32; i += 8)
        t[i][threadIdx.x] = Minv[(size_t)(by + i) * MF + bx + threadIdx.x];
    __syncthreads();
    for (int i = threadIdx.y; i < 32; i += 8) {
        int n = bx + i, k = by + threadIdx.x;
        __nv_bfloat16 h, l;
        bsplit(t[threadIdx.x][i], h, l);  // Minv[k][n] -> MinvT[n][k]
        g_mThi[(size_t)n * MF + k] = h;
        g_mTlo[(size_t)n * MF + k] = l;
    }
}

// ---------------- A_dot_b = x @ W^T ; seeds beff[0] split (u=v=0) ----------------
__global__ void gemm_nt_kernel(const float* __restrict__ X, const float* __restrict__ W) {
    __shared__ float As[16][64];
    __shared__ float Bs[16][64];
    int tid = threadIdx.x;
    int row0 = blockIdx.y * 64, col0 = blockIdx.x * 64;
    int lr = tid >> 2, kq = tid & 3;
    int tm = tid >> 4, tn = tid & 15;
    float acc[4][4] = {};
    for (int k0 = 0; k0 < NF; k0 += 16) {
        float4 a4 = *(const float4*)(X + (size_t)(row0 + lr) * NF + k0 + kq * 4);
        float4 b4 = *(const float4*)(W + (size_t)(col0 + lr) * NF + k0 + kq * 4);
        __syncthreads();
        As[kq * 4 + 0][lr] = a4.x; As[kq * 4 + 1][lr] = a4.y;
        As[kq * 4 + 2][lr] = a4.z; As[kq * 4 + 3][lr] = a4.w;
        Bs[kq * 4 + 0][lr] = b4.x; Bs[kq * 4 + 1][lr] = b4.y;
        Bs[kq * 4 + 2][lr] = b4.z; Bs[kq * 4 + 3][lr] = b4.w;
        __syncthreads();
#pragma unroll
        for (int kk = 0; kk < 16; kk++) {
            float4 av = *(const float4*)&As[kk][tm * 4];
            float4 bv = *(const float4*)&Bs[kk][tn * 4];
            float a[4] = {av.x, av.y, av.z, av.w};
            float b[4] = {bv.x, bv.y, bv.z, bv.w};
#pragma unroll
            for (int i = 0; i < 4; i++)
#pragma unroll
                for (int j = 0; j < 4; j++) acc[i][j] += a[i] * b[j];
        }
    }
#pragma unroll
    for (int i = 0; i < 4; i++) {
        size_t base = (size_t)(row0 + tm * 4 + i) * MF + col0 + tn * 4;
        *(float4*)(g_Adb + base) = make_float4(acc[i][0], acc[i][1], acc[i][2], acc[i][3]);
#pragma unroll
        for (int j = 0; j < 4; j++) {
            __nv_bfloat16 h, l;
            bsplit(acc[i][j], h, l);
            g_behi[0][base + j] = h;
            g_belo[0][base + j] = l;
        }
    }
}

// ---------------- per-iteration mma.sync GEMM + fused ADMM epilogue ----------------
// Tile 64(M) x 64(N); 4 warps as 2(M) x 2(N), warp tile 32x32.
// xk[r,n] = sum_k beff[r,k] * MinvT[n,k]; bf16 hi/lo 3-pass into fp32 frags.
// Fragment-level software pipeline: ldmatrix for k-step kk+1 overlaps MMAs of kk.
__global__ void __launch_bounds__(128, 3) admm_iter(int p) {
    if (g_stripe_done[blockIdx.y]) return;
    extern __shared__ __align__(16) char sraw[];
    __shared__ float red_dx[64][2];
    __shared__ float red_x2[64][2];

    const int tid = threadIdx.x;
    const int lane = tid & 31;
    const int w = tid >> 5;
    const int warp_m = w & 1;   // 2 warps x 32 rows
    const int warp_n = w >> 1;  // 2 warps x 32 cols
    const int row0 = blockIdx.y * 64;
    const int col0 = blockIdx.x * 64;
    const int pn = p ^ 1;

    const uint32_t sb = smem_u32(sraw);
    const int cs = tid & 7;

    // issue chunk 0
    {
        const __nv_bfloat16* ah = g_behi[p];
        const __nv_bfloat16* al = g_belo[p];
#pragma unroll
        for (int j = 0; j < 4; j++) {
            int row = (tid + j * 128) >> 3;
            uint32_t doff = (uint32_t)row * SROW2 + cs * 16;
            const size_t aoff = (size_t)(row0 + row) * MF + cs * 8;
            const size_t boff = (size_t)(col0 + row) * MF + cs * 8;
            cpa16(sb + doff, ah + aoff);
            cpa16(sb + TILEB + doff, al + aoff);
            cpa16(sb + 2 * TILEB + doff, g_mThi + boff);
            cpa16(sb + 3 * TILEB + doff, g_mTlo + boff);
        }
    }
    CP_COMMIT();

    float c[2][4][4] = {};
    // ldmatrix per-thread offsets
    const uint32_t a_off = (uint32_t)(warp_m * 32 + (lane & 15)) * SROW2 + (lane >> 4) * 16;
    const uint32_t b_off = (uint32_t)(warp_n * 32 + (lane & 7) + ((lane >> 4) & 1) * 8) * SROW2
                         + ((lane >> 3) & 1) * 16;

    // pipelined fragment buffers
    unsigned fah[2][2][4], fal[2][2][4], fbh[2][2][4], fbl[2][2][4];

    for (int t = 0; t < NCHUNK; t++) {
        int s = t & 1;
        if (t + 1 < NCHUNK) {
            int kb = (t + 1) * KC;
            uint32_t stb = sb + ((t + 1) & 1) * STAGEB;
            const __nv_bfloat16* ah = g_behi[p];
            const __nv_bfloat16* al = g_belo[p];
#pragma unroll
            for (int j = 0; j < 4; j++) {
                int row = (tid + j * 128) >> 3;
                uint32_t doff = (uint32_t)row * SROW2 + cs * 16;
                const size_t aoff = (size_t)(row0 + row) * MF + kb + cs * 8;
                const size_t boff = (size_t)(col0 + row) * MF + kb + cs * 8;
                cpa16(stb + doff, ah + aoff);
                cpa16(stb + TILEB + doff, al + aoff);
                cpa16(stb + 2 * TILEB + doff, g_mThi + boff);
                cpa16(stb + 3 * TILEB + doff, g_mTlo + boff);
            }
            CP_COMMIT();
            CP_WAIT(1);
        } else {
            CP_WAIT(0);
        }
        __syncthreads();

        const uint32_t Ah = sb + s * STAGEB;
        const uint32_t Al = Ah + TILEB;
        const uint32_t Bh = Ah + 2 * TILEB;
        const uint32_t Bl = Ah + 3 * TILEB;

        // preload kk=0 fragments into buffer 0
#pragma unroll
        for (int fm = 0; fm < 2; fm++) {
            uint32_t ao = a_off + (uint32_t)(fm * 16) * SROW2;
            ldm_x4(fah[0][fm], Ah + ao);
            ldm_x4(fal[0][fm], Al + ao);
        }
#pragma unroll
        for (int pr = 0; pr < 2; pr++) {
            uint32_t bo = b_off + (uint32_t)(pr * 16) * SROW2;
            ldm_x4(fbh[0][pr], Bh + bo);
            ldm_x4(fbl[0][pr], Bl + bo);
        }

#pragma unroll
        for (int kk = 0; kk < 4; kk++) {
            const int cur = kk & 1, nxt = cur ^ 1;
            if (kk < 3) {
                const uint32_t kb32 = (kk + 1) * 32;
#pragma unroll
                for (int fm = 0; fm < 2; fm++) {
                    uint32_t ao = a_off + (uint32_t)(fm * 16) * SROW2 + kb32;
                    ldm_x4(fah[nxt][fm], Ah + ao);
                    ldm_x4(fal[nxt][fm], Al + ao);
                }
#pragma unroll
                for (int pr = 0; pr < 2; pr++) {
                    uint32_t bo = b_off + (uint32_t)(pr * 16) * SROW2 + kb32;
                    ldm_x4(fbh[nxt][pr], Bh + bo);
                    ldm_x4(fbl[nxt][pr], Bl + bo);
                }
            }
#pragma unroll
            for (int fm = 0; fm < 2; fm++)
#pragma unroll
                for (int fn = 0; fn < 4; fn++) {
                    const unsigned* ph = &fbh[cur][fn >> 1][(fn & 1) * 2];
                    const unsigned* pl = &fbl[cur][fn >> 1][(fn & 1) * 2];
                    mma16816(c[fm][fn], fah[cur][fm], ph);
                    mma16816(c[fm][fn], fah[cur][fm], pl);
                    mma16816(c[fm][fn], fal[cur][fm], ph);
                }
        }
        __syncthreads();
    }

    // ---- fused ADMM epilogue on register fragments ----
    float pdx[2][2] = {}, px2[2][2] = {};
#pragma unroll
    for (int fm = 0; fm < 2; fm++) {
#pragma unroll
        for (int rs = 0; rs < 2; rs++) {
            int r = row0 + warp_m * 32 + fm * 16 + rs * 8 + (lane >> 2);
            int solved = g_solved[r];
            float ldx = 0.f, lx2 = 0.f;
#pragma unroll
            for (int fn = 0; fn < 4; fn++) {
                int cc = col0 + warp_n * 32 + fn * 8 + (lane & 3) * 2;
                size_t base = (size_t)r * MF + cc;
                float2 u2 = *(const float2*)(g_u + base);
                float2 v2 = *(const float2*)(g_v + base);
                float2 a2 = *(const float2*)(g_Adb + base);
                float uu[2] = {u2.x, u2.y}, vv[2] = {v2.x, v2.y}, aa[2] = {a2.x, a2.y};
                float un[2], vn[2];
#pragma unroll
                for (int jj = 0; jj < 2; jj++) {
                    float xk = c[fm][fn][rs * 2 + jj];
                    float tt = xk + uu[jj];
                    float av = fabsf(tt) - LAMBDv;
                    float sft = (av > 0.f) ? copysignf(av, tt) : 0.f;
                    if (!solved) {
                        un[jj] = tt - sft;
                        vn[jj] = sft;
                        float d = sft - vv[jj];
                        ldx += d * d;
                        lx2 += sft * sft;
                    } else {
                        un[jj] = uu[jj];
                        vn[jj] = vv[jj];
                    }
                }
                if (!solved) {
                    *(float2*)(g_u + base) = make_float2(un[0], un[1]);
                    *(float2*)(g_v + base) = make_float2(vn[0], vn[1]);
                }
                __nv_bfloat16 h0, l0, h1, l1;
                bsplit(aa[0] + vn[0] - un[0], h0, l0);
                bsplit(aa[1] + vn[1] - un[1], h1, l1);
                *(__nv_bfloat162*)(g_behi[pn] + base) = __halves2bfloat162(h0, h1);
                *(__nv_bfloat162*)(g_belo[pn] + base) = __halves2bfloat162(l0, l1);
            }
            pdx[fm][rs] = ldx;
            px2[fm][rs] = lx2;
        }
    }
    // reduce across the 4 column-lanes of each row
#pragma unroll
    for (int fm = 0; fm < 2; fm++) {
#pragma unroll
        for (int rs = 0; rs < 2; rs++) {
            float a = pdx[fm][rs], b = px2[fm][rs];
            a += __shfl_xor_sync(0xffffffffu, a, 1);
            a += __shfl_xor_sync(0xffffffffu, a, 2);
            b += __shfl_xor_sync(0xffffffffu, b, 1);
            b += __shfl_xor_sync(0xffffffffu, b, 2);
            if ((lane & 3) == 0) {
                int rl = warp_m * 32 + fm * 16 + rs * 8 + (lane >> 2);
                red_dx[rl][warp_n] = a;
                red_x2[rl][warp_n] = b;
            }
        }
    }
    __syncthreads();
    if (tid < 64) {
        int r = row0 + tid;
        g_dx2p[r * 16 + blockIdx.x] = red_dx[tid][0] + red_dx[tid][1];
        g_x2p[r * 16 + blockIdx.x] = red_x2[tid][0] + red_x2[tid][1];
    }
}

// ---------------- convergence flags + stripe-done ----------------
__global__ void converge_kernel() {
    int stripe = blockIdx.x;
    int r = stripe * 64 + threadIdx.x;
    __shared__ int cnt;
    if (threadIdx.x == 0) cnt = 0;
    __syncthreads();
    int slv = g_solved[r];
    if (!slv) {
        float sdx = 0.f, sx2 = 0.f;
#pragma unroll
        for (int j = 0; j < 16; j++) { sdx += g_dx2p[r * 16 + j]; sx2 += g_x2p[r * 16 + j]; }
        if (sdx < TOL2 * sx2) { g_solved[r] = 1; slv = 1; }
    }
    if (!slv) atomicAdd(&cnt, 1);
    __syncthreads();
    if (threadIdx.x == 0) g_stripe_done[stripe] = (cnt == 0);
}

// ---------------- enc = solved ? v : 0 ----------------
__global__ void finalize_enc(float* __restrict__ enc) {
    int i = blockIdx.x * blockDim.x + threadIdx.x;  // BATCH*MF/4
    int row = i / (MF / 4);
    float4 vv = ((const float4*)g_v)[i];
    float4 z = make_float4(0.f, 0.f, 0.f, 0.f);
    ((float4*)enc)[i] = g_solved[row] ? vv : z;
}

// ---------------- decoded = encoded @ W ----------------
__global__ void gemm_decode_kernel(const float* __restrict__ W, const float* __restrict__ enc,
                                   float* __restrict__ dec) {
    __shared__ float As[16][64];
    __shared__ float Bs[16][64];
    int tid = threadIdx.x;
    int row0 = blockIdx.y * 64, col0 = blockIdx.x * 64;
    int lr = tid >> 2, kq = tid & 3;
    int kr = tid >> 4, nq = tid & 15;
    int tm = tid >> 4, tn = tid & 15;
    float acc[4][4] = {};
    for (int k0 = 0; k0 < MF; k0 += 16) {
        float4 a4 = *(const float4*)(enc + (size_t)(row0 + lr) * MF + k0 + kq * 4);
        float4 b4 = *(const float4*)(W + (size_t)(k0 + kr) * NF + col0 + nq * 4);
        __syncthreads();
        As[kq * 4 + 0][lr] = a4.x; As[kq * 4 + 1][lr] = a4.y;
        As[kq * 4 + 2][lr] = a4.z; As[kq * 4 + 3][lr] = a4.w;
        *(float4*)&Bs[kr][nq * 4] = b4;
        __syncthreads();
#pragma unroll
        for (int kk = 0; kk < 16; kk++) {
            float4 av = *(const float4*)&As[kk][tm * 4];
            float4 bv = *(const float4*)&Bs[kk][tn * 4];
            float a[4] = {av.x, av.y, av.z, av.w};
            float b[4] = {bv.x, bv.y, bv.z, bv.w};
#pragma unroll
            for (int i = 0; i < 4; i++)
#pragma unroll
                for (int j = 0; j < 4; j++) acc[i][j] += a[i] * b[j];
        }
    }
#pragma unroll
    for (int i = 0; i < 4; i++) {
        float4 o = make_float4(acc[i][0], acc[i][1], acc[i][2], acc[i][3]);
        *(float4*)(dec + (size_t)(row0 + tm * 4 + i) * NF + col0 + tn * 4) = o;
    }
}

// ---------------- launch ----------------
extern "C" void kernel_launch(void* const* d_in, const int* in_sizes, int n_in,
                              void* d_out, int out_size) {
    const float* x = (const float*)d_in[0];      // (1024, 512)
    const float* w = (const float*)d_in[1];      // (1024, 512)
    const float* Minv = (const float*)d_in[2];   // (1024, 1024)
    float* out = (float*)d_out;
    float* enc = out;
    float* dec = out + BATCH * MF;

    static int attr_done = 0;
    if (!attr_done) {
        cudaFuncSetAttribute(admm_iter, cudaFuncAttributeMaxDynamicSharedMemorySize, DYN_SMEM);
        attr_done = 1;
    }

    init_kernel<<<BATCH * MF / 4 / 256, 256>>>();
    prep_minv<<<dim3(32, 32), dim3(32, 8)>>>(Minv);
    gemm_nt_kernel<<<dim3(MF / 64, BATCH / 64), 256>>>(x, w);

    for (int it = 0; it < MAX_ITERS; it++) {
        admm_iter<<<dim3(16, 16), 128, DYN_SMEM>>>(it & 1);
        converge_kernel<<<16, 64>>>();
    }

    finalize_enc<<<BATCH * MF / 4 / 256, 256>>>(enc);
    gemm_decode_kernel<<<dim3(NF / 64, BATCH / 64), 256>>>(w, enc, dec);
}

// round 12
// speedup vs baseline: 1.0230x; 1.0172x over previous
#include <cuda_runtime.h>
#include <cuda_bf16.h>
#include <cstdint>

#define BATCH 1024
#define MF 1024
#define NF 512
#define LAMBDv 0.2f
#define TOL2 1e-8f
#define MAX_ITERS 100

// iteration GEMM tiling: CTA tile 128(M) x 64(N), K chunks of 64, 512 threads
#define KC 64
#define NCHUNK (MF / KC)            // 16
#define SROW 72                     // smem row stride in bf16 (144B, ldmatrix conflict-free)
#define SROW2 (SROW * 2)
#define TILEB_A (128 * SROW2)       // 18432
#define TILEB_B (64 * SROW2)        // 9216
#define STAGEB (2 * TILEB_A + 2 * TILEB_B)  // 55296
#define DYN_SMEM (2 * STAGEB)       // 110592

// ---------------- device scratch ----------------
__device__ __align__(256) float g_Adb[BATCH * MF];
__device__ __align__(256) float g_u[BATCH * MF];
__device__ __align__(256) float g_v[BATCH * MF];
__device__ __align__(256) __nv_bfloat16 g_behi[2][BATCH * MF];
__device__ __align__(256) __nv_bfloat16 g_belo[2][BATCH * MF];
__device__ __align__(256) __nv_bfloat16 g_mThi[MF * MF];
__device__ __align__(256) __nv_bfloat16 g_mTlo[MF * MF];
__device__ float g_dx2p[BATCH * 16];
__device__ float g_x2p[BATCH * 16];
__device__ int g_solved[BATCH];
__device__ int g_stripe_done[8];
__device__ int g_stripe_cnt[8];

// ---------------- helpers ----------------
__device__ __forceinline__ uint32_t smem_u32(const void* p) {
    uint32_t a;
    asm("{ .reg .u64 t; cvta.to.shared.u64 t, %1; cvt.u32.u64 %0, t; }" : "=r"(a) : "l"(p));
    return a;
}
__device__ __forceinline__ void ldm_x4(unsigned* r, uint32_t addr) {
    asm volatile("ldmatrix.sync.aligned.m8n8.x4.shared.b16 {%0,%1,%2,%3}, [%4];"
        : "=r"(r[0]), "=r"(r[1]), "=r"(r[2]), "=r"(r[3]) : "r"(addr));
}
__device__ __forceinline__ void cpa16(uint32_t dst, const void* src) {
    asm volatile("cp.async.cg.shared.global [%0], [%1], 16;" :: "r"(dst), "l"(src));
}
#define CP_COMMIT() asm volatile("cp.async.commit_group;" ::: "memory")
#define CP_WAIT(n)  asm volatile("cp.async.wait_group %0;" :: "n"(n) : "memory")

__device__ __forceinline__ void mma16816(float* c, const unsigned* a, const unsigned* b) {
    asm volatile(
        "mma.sync.aligned.m16n8k16.row.col.f32.bf16.bf16.f32 "
        "{%0,%1,%2,%3}, {%4,%5,%6,%7}, {%8,%9}, {%0,%1,%2,%3};"
        : "+f"(c[0]), "+f"(c[1]), "+f"(c[2]), "+f"(c[3])
        : "r"(a[0]), "r"(a[1]), "r"(a[2]), "r"(a[3]), "r"(b[0]), "r"(b[1]));
}
__device__ __forceinline__ void bsplit(float x, __nv_bfloat16& h, __nv_bfloat16& l) {
    h = __float2bfloat16(x);
    l = __float2bfloat16(x - __bfloat162float(h));
}

// ---------------- init ----------------
__global__ void init_kernel() {
    int i = blockIdx.x * blockDim.x + threadIdx.x;  // BATCH*MF/4
    float4 z = make_float4(0.f, 0.f, 0.f, 0.f);
    ((float4*)g_u)[i] = z;
    ((float4*)g_v)[i] = z;
    if (i < BATCH) g_solved[i] = 0;
    if (i < 8) { g_stripe_done[i] = 0; g_stripe_cnt[i] = 0; }
}

// ---------------- Minv -> transposed bf16 hi/lo split ----------------
__global__ void prep_minv(const float* __restrict__ Minv) {
    __shared__ float t[32][33];
    int bx = blockIdx.x * 32, by = blockIdx.y * 32;
    for (int i = threadIdx.y; i < 32; i += 8)
        t[i][threadIdx.x] = Minv[(size_t)(by + i) * MF + bx + threadIdx.x];
    __syncthreads();
    for (int i = threadIdx.y; i < 32; i += 8) {
        int n = bx + i, k = by + threadIdx.x;
        __nv_bfloat16 h, l;
        bsplit(t[threadIdx.x][i], h, l);  // Minv[k][n] -> MinvT[n][k]
        g_mThi[(size_t)n * MF + k] = h;
        g_mTlo[(size_t)n * MF + k] = l;
    }
}

// ---------------- A_dot_b = x @ W^T ; seeds beff[0] split (u=v=0) ----------------
__global__ void gemm_nt_kernel(const float* __restrict__ X, const float* __restrict__ W) {
    __shared__ float As[16][64];
    __shared__ float Bs[16][64];
    int tid = threadIdx.x;
    int row0 = blockIdx.y * 64, col0 = blockIdx.x * 64;
    int lr = tid >> 2, kq = tid & 3;
    int tm = tid >> 4, tn = tid & 15;
    float acc[4][4] = {};
    for (int k0 = 0; k0 < NF; k0 += 16) {
        float4 a4 = *(const float4*)(X + (size_t)(row0 + lr) * NF + k0 + kq * 4);
        float4 b4 = *(const float4*)(W + (size_t)(col0 + lr) * NF + k0 + kq * 4);
        __syncthreads();
        As[kq * 4 + 0][lr] = a4.x; As[kq * 4 + 1][lr] = a4.y;
        As[kq * 4 + 2][lr] = a4.z; As[kq * 4 + 3][lr] = a4.w;
        Bs[kq * 4 + 0][lr] = b4.x; Bs[kq * 4 + 1][lr] = b4.y;
        Bs[kq * 4 + 2][lr] = b4.z; Bs[kq * 4 + 3][lr] = b4.w;
        __syncthreads();
#pragma unroll
        for (int kk = 0; kk < 16; kk++) {
            float4 av = *(const float4*)&As[kk][tm * 4];
            float4 bv = *(const float4*)&Bs[kk][tn * 4];
            float a[4] = {av.x, av.y, av.z, av.w};
            float b[4] = {bv.x, bv.y, bv.z, bv.w};
#pragma unroll
            for (int i = 0; i < 4; i++)
#pragma unroll
                for (int j = 0; j < 4; j++) acc[i][j] += a[i] * b[j];
        }
    }
#pragma unroll
    for (int i = 0; i < 4; i++) {
        size_t base = (size_t)(row0 + tm * 4 + i) * MF + col0 + tn * 4;
        *(float4*)(g_Adb + base) = make_float4(acc[i][0], acc[i][1], acc[i][2], acc[i][3]);
#pragma unroll
        for (int j = 0; j < 4; j++) {
            __nv_bfloat16 h, l;
            bsplit(acc[i][j], h, l);
            g_behi[0][base + j] = h;
            g_belo[0][base + j] = l;
        }
    }
}

// ---------------- per-iteration mma.sync GEMM + fused ADMM epilogue + converge ----------------
// Tile 128(M) x 64(N); 16 warps as 4(M) x 4(N), warp tile 32x16.
// xk[r,n] = sum_k beff[r,k] * MinvT[n,k]; bf16 hi/lo 3-pass into fp32 frags.
__global__ void __launch_bounds__(512, 1) admm_iter(int p) {
    if (g_stripe_done[blockIdx.y]) return;
    extern __shared__ __align__(16) char sraw[];
    __shared__ float red_dx[128][4];
    __shared__ float red_x2[128][4];
    __shared__ int s_last, s_cnt;

    const int tid = threadIdx.x;
    const int lane = tid & 31;
    const int w = tid >> 5;
    const int warp_m = w & 3;   // 4 warps x 32 rows
    const int warp_n = w >> 2;  // 4 warps x 16 cols
    const int row0 = blockIdx.y * 128;
    const int col0 = blockIdx.x * 64;
    const int pn = p ^ 1;

    const uint32_t sb = smem_u32(sraw);
    const int cs = tid & 7;
    const int rA0 = (tid) >> 3, rA1 = (tid + 512) >> 3;  // A rows (0..127)
    const int rB = tid >> 3;                              // B row (0..63)

    // issue chunk 0
    {
        const __nv_bfloat16* ah = g_behi[p];
        const __nv_bfloat16* al = g_belo[p];
        uint32_t d0 = (uint32_t)rA0 * SROW2 + cs * 16;
        uint32_t d1 = (uint32_t)rA1 * SROW2 + cs * 16;
        size_t s0 = (size_t)(row0 + rA0) * MF + cs * 8;
        size_t s1 = (size_t)(row0 + rA1) * MF + cs * 8;
        cpa16(sb + d0, ah + s0);
        cpa16(sb + d1, ah + s1);
        cpa16(sb + TILEB_A + d0, al + s0);
        cpa16(sb + TILEB_A + d1, al + s1);
        uint32_t db = (uint32_t)rB * SROW2 + cs * 16;
        size_t sB = (size_t)(col0 + rB) * MF + cs * 8;
        cpa16(sb + 2 * TILEB_A + db, g_mThi + sB);
        cpa16(sb + 2 * TILEB_A + TILEB_B + db, g_mTlo + sB);
    }
    CP_COMMIT();

    float c[2][2][4] = {};
    const uint32_t a_off = (uint32_t)(warp_m * 32 + (lane & 15)) * SROW2 + (lane >> 4) * 16;
    const uint32_t b_off = (uint32_t)(warp_n * 16 + (lane & 7) + ((lane >> 4) & 1) * 8) * SROW2
                         + ((lane >> 3) & 1) * 16;

    for (int t = 0; t < NCHUNK; t++) {
        int s = t & 1;
        if (t + 1 < NCHUNK) {
            int kb = (t + 1) * KC;
            uint32_t stb = sb + ((t + 1) & 1) * STAGEB;
            const __nv_bfloat16* ah = g_behi[p];
            const __nv_bfloat16* al = g_belo[p];
            uint32_t d0 = (uint32_t)rA0 * SROW2 + cs * 16;
            uint32_t d1 = (uint32_t)rA1 * SROW2 + cs * 16;
            size_t s0 = (size_t)(row0 + rA0) * MF + kb + cs * 8;
            size_t s1 = (size_t)(row0 + rA1) * MF + kb + cs * 8;
            cpa16(stb + d0, ah + s0);
            cpa16(stb + d1, ah + s1);
            cpa16(stb + TILEB_A + d0, al + s0);
            cpa16(stb + TILEB_A + d1, al + s1);
            uint32_t db = (uint32_t)rB * SROW2 + cs * 16;
            size_t sB = (size_t)(col0 + rB) * MF + kb + cs * 8;
            cpa16(stb + 2 * TILEB_A + db, g_mThi + sB);
            cpa16(stb + 2 * TILEB_A + TILEB_B + db, g_mTlo + sB);
            CP_COMMIT();
            CP_WAIT(1);
        } else {
            CP_WAIT(0);
        }
        __syncthreads();

        const uint32_t Ah = sb + s * STAGEB;
        const uint32_t Al = Ah + TILEB_A;
        const uint32_t Bh = Ah + 2 * TILEB_A;
        const uint32_t Bl = Bh + TILEB_B;
#pragma unroll
        for (int kk = 0; kk < 4; kk++) {
            const uint32_t kb32 = kk * 32;
            unsigned ah[2][4], al[2][4], bh[4], bl[4];
#pragma unroll
            for (int fm = 0; fm < 2; fm++) {
                uint32_t ao = a_off + (uint32_t)(fm * 16) * SROW2 + kb32;
                ldm_x4(ah[fm], Ah + ao);
                ldm_x4(al[fm], Al + ao);
            }
            ldm_x4(bh, Bh + b_off + kb32);
            ldm_x4(bl, Bl + b_off + kb32);
#pragma unroll
            for (int fm = 0; fm < 2; fm++)
#pragma unroll
                for (int fn = 0; fn < 2; fn++) {
                    const unsigned* ph = &bh[fn * 2];
                    const unsigned* pl = &bl[fn * 2];
                    mma16816(c[fm][fn], ah[fm], ph);
                    mma16816(c[fm][fn], ah[fm], pl);
                    mma16816(c[fm][fn], al[fm], ph);
                }
        }
        __syncthreads();
    }

    // ---- fused ADMM epilogue on register fragments ----
    float pdx[2][2] = {}, px2[2][2] = {};
#pragma unroll
    for (int fm = 0; fm < 2; fm++) {
#pragma unroll
        for (int rs = 0; rs < 2; rs++) {
            int r = row0 + warp_m * 32 + fm * 16 + rs * 8 + (lane >> 2);
            int solved = g_solved[r];
            float ldx = 0.f, lx2 = 0.f;
#pragma unroll
            for (int fn = 0; fn < 2; fn++) {
                int cc = col0 + warp_n * 16 + fn * 8 + (lane & 3) * 2;
                size_t base = (size_t)r * MF + cc;
                float2 u2 = *(const float2*)(g_u + base);
                float2 v2 = *(const float2*)(g_v + base);
                float2 a2 = *(const float2*)(g_Adb + base);
                float uu[2] = {u2.x, u2.y}, vv[2] = {v2.x, v2.y}, aa[2] = {a2.x, a2.y};
                float un[2], vn[2];
#pragma unroll
                for (int jj = 0; jj < 2; jj++) {
                    float xk = c[fm][fn][rs * 2 + jj];
                    float tt = xk + uu[jj];
                    float av = fabsf(tt) - LAMBDv;
                    float sft = (av > 0.f) ? copysignf(av, tt) : 0.f;
                    if (!solved) {
                        un[jj] = tt - sft;
                        vn[jj] = sft;
                        float d = sft - vv[jj];
                        ldx += d * d;
                        lx2 += sft * sft;
                    } else {
                        un[jj] = uu[jj];
                        vn[jj] = vv[jj];
                    }
                }
                if (!solved) {
                    *(float2*)(g_u + base) = make_float2(un[0], un[1]);
                    *(float2*)(g_v + base) = make_float2(vn[0], vn[1]);
                }
                __nv_bfloat16 h0, l0, h1, l1;
                bsplit(aa[0] + vn[0] - un[0], h0, l0);
                bsplit(aa[1] + vn[1] - un[1], h1, l1);
                *(__nv_bfloat162*)(g_behi[pn] + base) = __halves2bfloat162(h0, h1);
                *(__nv_bfloat162*)(g_belo[pn] + base) = __halves2bfloat162(l0, l1);
            }
            pdx[fm][rs] = ldx;
            px2[fm][rs] = lx2;
        }
    }
    // reduce across the 4 column-lanes of each row
#pragma unroll
    for (int fm = 0; fm < 2; fm++) {
#pragma unroll
        for (int rs = 0; rs < 2; rs++) {
            float a = pdx[fm][rs], b = px2[fm][rs];
            a += __shfl_xor_sync(0xffffffffu, a, 1);
            a += __shfl_xor_sync(0xffffffffu, a, 2);
            b += __shfl_xor_sync(0xffffffffu, b, 1);
            b += __shfl_xor_sync(0xffffffffu, b, 2);
            if ((lane & 3) == 0) {
                int rl = warp_m * 32 + fm * 16 + rs * 8 + (lane >> 2);
                red_dx[rl][warp_n] = a;
                red_x2[rl][warp_n] = b;
            }
        }
    }
    __syncthreads();
    if (tid < 128) {
        int r = row0 + tid;
        g_dx2p[r * 16 + blockIdx.x] = red_dx[tid][0] + red_dx[tid][1] + red_dx[tid][2] + red_dx[tid][3];
        g_x2p[r * 16 + blockIdx.x] = red_x2[tid][0] + red_x2[tid][1] + red_x2[tid][2] + red_x2[tid][3];
    }

    // ---- last CTA of this stripe performs the convergence reduction ----
    __threadfence();
    __syncthreads();
    if (tid == 0) s_last = (atomicAdd(&g_stripe_cnt[blockIdx.y], 1) == 15);
    __syncthreads();
    if (s_last) {
        if (tid == 0) s_cnt = 0;
        __syncthreads();
        int active = 0;
        if (tid < 128) {
            int r = row0 + tid;
            int slv = g_solved[r];
            if (!slv) {
                float sdx = 0.f, sx2 = 0.f;
#pragma unroll
                for (int j = 0; j < 16; j++) { sdx += g_dx2p[r * 16 + j]; sx2 += g_x2p[r * 16 + j]; }
                if (sdx < TOL2 * sx2) { g_solved[r] = 1; slv = 1; }
            }
            active = !slv;
        }
        if (active) atomicAdd(&s_cnt, 1);
        __syncthreads();
        if (tid == 0) {
            g_stripe_done[blockIdx.y] = (s_cnt == 0);
            g_stripe_cnt[blockIdx.y] = 0;
        }
    }
}

// ---------------- enc = solved ? v : 0 ----------------
__global__ void finalize_enc(float* __restrict__ enc) {
    int i = blockIdx.x * blockDim.x + threadIdx.x;  // BATCH*MF/4
    int row = i / (MF / 4);
    float4 vv = ((const float4*)g_v)[i];
    float4 z = make_float4(0.f, 0.f, 0.f, 0.f);
    ((float4*)enc)[i] = g_solved[row] ? vv : z;
}

// ---------------- decoded = encoded @ W ----------------
__global__ void gemm_decode_kernel(const float* __restrict__ W, const float* __restrict__ enc,
                                   float* __restrict__ dec) {
    __shared__ float As[16][64];
    __shared__ float Bs[16][64];
    int tid = threadIdx.x;
    int row0 = blockIdx.y * 64, col0 = blockIdx.x * 64;
    int lr = tid >> 2, kq = tid & 3;
    int kr = tid >> 4, nq = tid & 15;
    int tm = tid >> 4, tn = tid & 15;
    float acc[4][4] = {};
    for (int k0 = 0; k0 < MF; k0 += 16) {
        float4 a4 = *(const float4*)(enc + (size_t)(row0 + lr) * MF + k0 + kq * 4);
        float4 b4 = *(const float4*)(W + (size_t)(k0 + kr) * NF + col0 + nq * 4);
        __syncthreads();
        As[kq * 4 + 0][lr] = a4.x; As[kq * 4 + 1][lr] = a4.y;
        As[kq * 4 + 2][lr] = a4.z; As[kq * 4 + 3][lr] = a4.w;
        *(float4*)&Bs[kr][nq * 4] = b4;
        __syncthreads();
#pragma unroll
        for (int kk = 0; kk < 16; kk++) {
            float4 av = *(const float4*)&As[kk][tm * 4];
            float4 bv = *(const float4*)&Bs[kk][tn * 4];
            float a[4] = {av.x, av.y, av.z, av.w};
            float b[4] = {bv.x, bv.y, bv.z, bv.w};
#pragma unroll
            for (int i = 0; i < 4; i++)
#pragma unroll
                for (int j = 0; j < 4; j++) acc[i][j] += a[i] * b[j];
        }
    }
#pragma unroll
    for (int i = 0; i < 4; i++) {
        float4 o = make_float4(acc[i][0], acc[i][1], acc[i][2], acc[i][3]);
        *(float4*)(dec + (size_t)(row0 + tm * 4 + i) * NF + col0 + tn * 4) = o;
    }
}

// ---------------- launch ----------------
extern "C" void kernel_launch(void* const* d_in, const int* in_sizes, int n_in,
                              void* d_out, int out_size) {
    const float* x = (const float*)d_in[0];      // (1024, 512)
    const float* w = (const float*)d_in[1];      // (1024, 512)
    const float* Minv = (const float*)d_in[2];   // (1024, 1024)
    float* out = (float*)d_out;
    float* enc = out;
    float* dec = out + BATCH * MF;

    static int attr_done = 0;
    if (!attr_done) {
        cudaFuncSetAttribute(admm_iter, cudaFuncAttributeMaxDynamicSharedMemorySize, DYN_SMEM);
        attr_done = 1;
    }

    init_kernel<<<BATCH * MF / 4 / 256, 256>>>();
    prep_minv<<<dim3(32, 32), dim3(32, 8)>>>(Minv);
    gemm_nt_kernel<<<dim3(MF / 64, BATCH / 64), 256>>>(x, w);

    for (int it = 0; it < MAX_ITERS; it++) {
        admm_iter<<<dim3(16, 8), 512, DYN_SMEM>>>(it & 1);
    }

    finalize_enc<<<BATCH * MF / 4 / 256, 256>>>(enc);
    gemm_decode_kernel<<<dim3(NF / 64, BATCH / 64), 256>>>(w, enc, dec);
}